// round 2
// baseline (speedup 1.0000x reference)
#include <cuda_runtime.h>

#define NUM_NODES 65536
#define NGRAPH    1024
#define GSIZE     64
#define HID       256
#define NH1       128
#define EDGES     2097152

// ---------------- scratch (no allocations allowed) ----------------
__device__ int g_deg[NUM_NODES];

// ---------------- degree histogram ----------------
__global__ void deg_kernel(const int* __restrict__ src) {
    int i = blockIdx.x * blockDim.x + threadIdx.x;        // over EDGES/4 int4s
    int4 v = reinterpret_cast<const int4*>(src)[i];
    atomicAdd(&g_deg[v.x], 1);
    atomicAdd(&g_deg[v.y], 1);
    atomicAdd(&g_deg[v.z], 1);
    atomicAdd(&g_deg[v.w], 1);
}

// ---------------- f32x2 helpers ----------------
__device__ __forceinline__ unsigned long long pack2(float lo, float hi) {
    unsigned long long r;
    asm("mov.b64 %0, {%1, %2};" : "=l"(r) : "f"(lo), "f"(hi));
    return r;
}
__device__ __forceinline__ float2 unpack2(unsigned long long v) {
    float2 f;
    asm("mov.b64 {%0, %1}, %2;" : "=f"(f.x), "=f"(f.y) : "l"(v));
    return f;
}
__device__ __forceinline__ unsigned long long ffma2(unsigned long long a,
                                                    unsigned long long b,
                                                    unsigned long long c) {
    unsigned long long d;
    asm("fma.rn.f32x2 %0, %1, %2, %3;" : "=l"(d) : "l"(a), "l"(b), "l"(c));
    return d;
}
__device__ __forceinline__ float silu(float x) {
    return x / (1.0f + __expf(-x));
}

// ---------------- smem layout (bytes) ----------------
// sAdup : [32][65] u64   @ 0       (16640 B)  -- A tile, lane-duplicated pairs
// sB    : [32][132] f32  @ 16640   (16896 B)  -- W tile (K-major rows)
// sH    : [64][132] f32  @ 33536   (33792 B)  -- H1 after silu (also sDeg early)
// sC    : 512 f32        @ 67328   (2048 B)   -- b1 | b2 | W3 | W1row0
// sConn : 64 f32         @ 69376   (256 B)
// sLog  : 64 f32         @ 69632   (256 B)
#define OFF_ADUP 0
#define OFF_B    16640
#define OFF_H    33536
#define OFF_C    67328
#define OFF_CONN 69376
#define OFF_LOG  69632
#define SMEM_BYTES 69888

__device__ __forceinline__ void gemm_inner(const unsigned long long* __restrict__ sAdup,
                                           const float* __restrict__ sB,
                                           int tx, int ty,
                                           unsigned long long acc[8][4]) {
#pragma unroll 4
    for (int k = 0; k < 32; ++k) {
        unsigned long long aD[8];
#pragma unroll
        for (int i = 0; i < 8; ++i) aD[i] = sAdup[k * 65 + ty * 8 + i];
        ulonglong2 bq0 = *reinterpret_cast<const ulonglong2*>(sB + k * 132 + tx * 8);
        ulonglong2 bq1 = *reinterpret_cast<const ulonglong2*>(sB + k * 132 + tx * 8 + 4);
        unsigned long long bp[4] = {bq0.x, bq0.y, bq1.x, bq1.y};
#pragma unroll
        for (int i = 0; i < 8; ++i)
#pragma unroll
            for (int jp = 0; jp < 4; ++jp)
                acc[i][jp] = ffma2(aD[i], bp[jp], acc[i][jp]);
    }
}

__global__ void __launch_bounds__(128, 3)
mlp_kernel(const float* __restrict__ X,  const float* __restrict__ W1,
           const float* __restrict__ b1, const float* __restrict__ W2,
           const float* __restrict__ b2, const float* __restrict__ W3,
           const float* __restrict__ b3, const float* __restrict__ kT,
           float* __restrict__ out) {
    extern __shared__ char smem[];
    unsigned long long* sAdup = reinterpret_cast<unsigned long long*>(smem + OFF_ADUP);
    float* sB    = reinterpret_cast<float*>(smem + OFF_B);
    float* sH    = reinterpret_cast<float*>(smem + OFF_H);
    float* sC    = reinterpret_cast<float*>(smem + OFF_C);
    float* sConn = reinterpret_cast<float*>(smem + OFF_CONN);
    float* sLog  = reinterpret_cast<float*>(smem + OFF_LOG);

    const int tid  = threadIdx.x;
    const int g    = blockIdx.x;
    const int row0 = g * GSIZE;
    const int tx   = tid & 15;
    const int ty   = tid >> 4;

    // ---- constants into smem ----
    sC[tid]       = b1[tid];
    sC[128 + tid] = b2[tid];
    sC[256 + tid] = W3[tid];
    sC[384 + tid] = W1[tid];          // W1 row 0 (the conn column)
    float b3v = __ldg(b3);
    float ikT = 1.0f / __ldg(kT);

    // ---- connectivity feature: stable per-graph degree rank ----
    int* sDeg = reinterpret_cast<int*>(sH);   // sH unused this early
    if (tid < GSIZE) sDeg[tid] = g_deg[row0 + tid];
    __syncthreads();
    if (tid < GSIZE) {
        int di = sDeg[tid];
        int r  = 0;
#pragma unroll 8
        for (int j = 0; j < GSIZE; ++j) {
            int dj = sDeg[j];
            r += (dj < di) || (dj == di && j < tid);
        }
        sConn[r] = (float)tid * (1.0f / 64.0f);
    }
    __syncthreads();

    // ---- GEMM1: H1 = silu([conn | X] @ W1 + b1), tile 64x128, K=257 ----
    unsigned long long acc[8][4];
    {
        float cr[8];
#pragma unroll
        for (int i = 0; i < 8; ++i) cr[i] = sConn[ty * 8 + i];
#pragma unroll
        for (int jp = 0; jp < 4; ++jp) {
            int c   = tx * 8 + 2 * jp;
            float wa = sC[384 + c], wb = sC[384 + c + 1];
            float ba = sC[c],       bb = sC[c + 1];
#pragma unroll
            for (int i = 0; i < 8; ++i)
                acc[i][jp] = pack2(fmaf(cr[i], wa, ba), fmaf(cr[i], wb, bb));
        }
    }

    for (int kc = 0; kc < 8; ++kc) {
        int f0 = kc * 32;
        // A tile: X[row0..row0+63][f0..f0+31], store duplicated pairs
#pragma unroll
        for (int p = 0; p < 4; ++p) {
            int v = tid + 128 * p;            // 0..511
            int m = v >> 3, k4 = v & 7;
            float4 x4 = *reinterpret_cast<const float4*>(
                X + (size_t)(row0 + m) * HID + f0 + 4 * k4);
            sAdup[(4 * k4 + 0) * 65 + m] = pack2(x4.x, x4.x);
            sAdup[(4 * k4 + 1) * 65 + m] = pack2(x4.y, x4.y);
            sAdup[(4 * k4 + 2) * 65 + m] = pack2(x4.z, x4.z);
            sAdup[(4 * k4 + 3) * 65 + m] = pack2(x4.w, x4.w);
        }
        // B tile: W1 rows [1+f0, 1+f0+32)
#pragma unroll
        for (int p = 0; p < 8; ++p) {
            int v = tid + 128 * p;            // 0..1023
            int k = v >> 5, n4 = v & 31;
            float4 w = *reinterpret_cast<const float4*>(
                W1 + (size_t)(1 + f0 + k) * NH1 + 4 * n4);
            *reinterpret_cast<float4*>(sB + k * 132 + 4 * n4) = w;
        }
        __syncthreads();
        gemm_inner(sAdup, sB, tx, ty, acc);
        __syncthreads();
    }

    // epilogue: silu -> sH
#pragma unroll
    for (int i = 0; i < 8; ++i) {
        int row = ty * 8 + i;
#pragma unroll
        for (int jp = 0; jp < 4; ++jp) {
            float2 v = unpack2(acc[i][jp]);
            int col = tx * 8 + 2 * jp;
            sH[row * 132 + col]     = silu(v.x);
            sH[row * 132 + col + 1] = silu(v.y);
        }
    }
    __syncthreads();

    // ---- GEMM2: H2pre = H1 @ W2 + b2, K=128 ----
#pragma unroll
    for (int jp = 0; jp < 4; ++jp) {
        int c = tx * 8 + 2 * jp;
        unsigned long long binit = pack2(sC[128 + c], sC[128 + c + 1]);
#pragma unroll
        for (int i = 0; i < 8; ++i) acc[i][jp] = binit;
    }

    for (int kc = 0; kc < 4; ++kc) {
        int k0 = kc * 32;
        // A tile: duplicated pairs from sH
#pragma unroll
        for (int p = 0; p < 4; ++p) {
            int v = tid + 128 * p;
            int m = v >> 3, k4 = v & 7;
            float4 h4 = *reinterpret_cast<const float4*>(sH + m * 132 + k0 + 4 * k4);
            sAdup[(4 * k4 + 0) * 65 + m] = pack2(h4.x, h4.x);
            sAdup[(4 * k4 + 1) * 65 + m] = pack2(h4.y, h4.y);
            sAdup[(4 * k4 + 2) * 65 + m] = pack2(h4.z, h4.z);
            sAdup[(4 * k4 + 3) * 65 + m] = pack2(h4.w, h4.w);
        }
        // B tile: W2 rows [k0, k0+32)
#pragma unroll
        for (int p = 0; p < 8; ++p) {
            int v = tid + 128 * p;
            int k = v >> 5, n4 = v & 31;
            float4 w = *reinterpret_cast<const float4*>(
                W2 + (size_t)(k0 + k) * NH1 + 4 * n4);
            *reinterpret_cast<float4*>(sB + k * 132 + 4 * n4) = w;
        }
        __syncthreads();
        gemm_inner(sAdup, sB, tx, ty, acc);
        __syncthreads();
    }

    // ---- layer 3 partials: silu(H2pre) . W3 ----
    float part[8];
#pragma unroll
    for (int i = 0; i < 8; ++i) {
        float s = 0.0f;
#pragma unroll
        for (int jp = 0; jp < 4; ++jp) {
            float2 v = unpack2(acc[i][jp]);
            int col = tx * 8 + 2 * jp;
            s = fmaf(silu(v.x), sC[256 + col], s);
            s = fmaf(silu(v.y), sC[256 + col + 1], s);
        }
        part[i] = s;
    }
    float* sPart = reinterpret_cast<float*>(smem);   // overlay sAdup [64][17]
#pragma unroll
    for (int i = 0; i < 8; ++i) sPart[(ty * 8 + i) * 17 + tx] = part[i];
    __syncthreads();

    if (tid < GSIZE) {
        float s = 0.0f;
#pragma unroll
        for (int t = 0; t < 16; ++t) s += sPart[tid * 17 + t];
        sLog[tid] = (s + b3v) * ikT;
    }
    __syncthreads();

    // ---- per-graph softmax (warp 0 handles all 64 logits) ----
    if (tid < 32) {
        float a  = sLog[tid];
        float b  = sLog[tid + 32];
        float mx = fmaxf(a, b);
#pragma unroll
        for (int o = 16; o; o >>= 1) mx = fmaxf(mx, __shfl_xor_sync(0xffffffffu, mx, o));
        float e0 = expf(a - mx);
        float e1 = expf(b - mx);
        float s  = e0 + e1;
#pragma unroll
        for (int o = 16; o; o >>= 1) s += __shfl_xor_sync(0xffffffffu, s, o);
        float inv = 1.0f / s;
        out[row0 + tid]      = e0 * inv;
        out[row0 + tid + 32] = e1 * inv;
    }
}

// ---------------- launcher ----------------
extern "C" void kernel_launch(void* const* d_in, const int* in_sizes, int n_in,
                              void* d_out, int out_size) {
    const float* X  = (const float*)d_in[0];
    const float* W1 = (const float*)d_in[1];
    const float* b1 = (const float*)d_in[2];
    const float* W2 = (const float*)d_in[3];
    const float* b2 = (const float*)d_in[4];
    const float* W3 = (const float*)d_in[5];
    const float* b3 = (const float*)d_in[6];
    const float* kT = (const float*)d_in[7];
    const int*   ei = (const int*)d_in[8];
    float* out = (float*)d_out;

    void* degPtr = nullptr;
    cudaGetSymbolAddress(&degPtr, g_deg);
    cudaMemsetAsync(degPtr, 0, NUM_NODES * sizeof(int));

    deg_kernel<<<EDGES / 4 / 256, 256>>>(ei);

    cudaFuncSetAttribute(mlp_kernel, cudaFuncAttributeMaxDynamicSharedMemorySize,
                         SMEM_BYTES);
    mlp_kernel<<<NGRAPH, 128, SMEM_BYTES>>>(X, W1, b1, W2, b2, W3, b3, kT, out);
}

// round 4
// speedup vs baseline: 1.0015x; 1.0015x over previous
#include <cuda_runtime.h>

#define NUM_NODES 65536
#define NGRAPH    1024
#define GSIZE     64
#define HID       256
#define NH1       128
#define EDGES     2097152

// ---------------- scratch ----------------
__device__ int g_deg[NUM_NODES];

// ---------------- degree histogram ----------------
__global__ void deg_kernel(const int* __restrict__ src) {
    int i = blockIdx.x * blockDim.x + threadIdx.x;
    int4 v = reinterpret_cast<const int4*>(src)[i];
    atomicAdd(&g_deg[v.x], 1);
    atomicAdd(&g_deg[v.y], 1);
    atomicAdd(&g_deg[v.z], 1);
    atomicAdd(&g_deg[v.w], 1);
}

// ---------------- f32x2 helpers ----------------
__device__ __forceinline__ unsigned long long pack2(float lo, float hi) {
    unsigned long long r;
    asm("mov.b64 %0, {%1, %2};" : "=l"(r) : "f"(lo), "f"(hi));
    return r;
}
__device__ __forceinline__ float2 unpack2(unsigned long long v) {
    float2 f;
    asm("mov.b64 {%0, %1}, %2;" : "=f"(f.x), "=f"(f.y) : "l"(v));
    return f;
}
__device__ __forceinline__ unsigned long long ffma2(unsigned long long a,
                                                    unsigned long long b,
                                                    unsigned long long c) {
    unsigned long long d;
    asm("fma.rn.f32x2 %0, %1, %2, %3;" : "=l"(d) : "l"(a), "l"(b), "l"(c));
    return d;
}
__device__ __forceinline__ float silu(float x) {
    return x / (1.0f + __expf(-x));
}

// ---------------- smem layout (bytes) ----------------
// sA : [32][138] f32  @ 0       (17664)  A tile, NATURAL f32, k-major
// sB : [32][132] f32  @ 17664   (16896)  W tile, k-major
// sH : [128][132] f32 @ 34560   (67584)  H1 (also sDeg early)
// sC : 512 f32        @ 102144  (2048)   b1 | b2 | W3 | W1row0
// sConn : 128 f32     @ 104192  (512)
// sLog  : 128 f32     @ 104704  (512)
#define OFF_A    0
#define OFF_B    17664
#define OFF_H    34560
#define OFF_C    102144
#define OFF_CONN 104192
#define OFF_LOG  104704
#define SMEM_BYTES 105216

#define APITCH 138
#define BPITCH 132
#define HPITCH 132

// inner GEMM over a 32-k chunk: A natural f32, dup into regs
__device__ __forceinline__ void gemm_inner(const float* __restrict__ sA,
                                           const float* __restrict__ sB,
                                           int tx, int ty,
                                           unsigned long long acc[8][4]) {
#pragma unroll 2
    for (int k = 0; k < 32; ++k) {
        float2 a01 = *reinterpret_cast<const float2*>(sA + k * APITCH + ty * 8 + 0);
        float2 a23 = *reinterpret_cast<const float2*>(sA + k * APITCH + ty * 8 + 2);
        float2 a45 = *reinterpret_cast<const float2*>(sA + k * APITCH + ty * 8 + 4);
        float2 a67 = *reinterpret_cast<const float2*>(sA + k * APITCH + ty * 8 + 6);
        ulonglong2 bq0 = *reinterpret_cast<const ulonglong2*>(sB + k * BPITCH + tx * 8);
        ulonglong2 bq1 = *reinterpret_cast<const ulonglong2*>(sB + k * BPITCH + tx * 8 + 4);
        unsigned long long bp[4] = {bq0.x, bq0.y, bq1.x, bq1.y};
        unsigned long long aD[8];
        aD[0] = pack2(a01.x, a01.x); aD[1] = pack2(a01.y, a01.y);
        aD[2] = pack2(a23.x, a23.x); aD[3] = pack2(a23.y, a23.y);
        aD[4] = pack2(a45.x, a45.x); aD[5] = pack2(a45.y, a45.y);
        aD[6] = pack2(a67.x, a67.x); aD[7] = pack2(a67.y, a67.y);
#pragma unroll
        for (int i = 0; i < 8; ++i)
#pragma unroll
            for (int jp = 0; jp < 4; ++jp)
                acc[i][jp] = ffma2(aD[i], bp[jp], acc[i][jp]);
    }
}

// CTA = 2 graphs (128 rows), 256 threads, thread tile 8x8
__global__ void __launch_bounds__(256, 2)
mlp_kernel(const float* __restrict__ X,  const float* __restrict__ W1,
           const float* __restrict__ b1, const float* __restrict__ W2,
           const float* __restrict__ b2, const float* __restrict__ W3,
           const float* __restrict__ b3, const float* __restrict__ kT,
           float* __restrict__ out) {
    extern __shared__ char smem[];
    float* sA    = reinterpret_cast<float*>(smem + OFF_A);
    float* sB    = reinterpret_cast<float*>(smem + OFF_B);
    float* sH    = reinterpret_cast<float*>(smem + OFF_H);
    float* sC    = reinterpret_cast<float*>(smem + OFF_C);
    float* sConn = reinterpret_cast<float*>(smem + OFF_CONN);
    float* sLog  = reinterpret_cast<float*>(smem + OFF_LOG);

    const int tid  = threadIdx.x;
    const int row0 = blockIdx.x * 128;      // 2 graphs per CTA
    const int tx   = tid & 15;
    const int ty   = tid >> 4;

    // ---- constants ----
    if (tid < 128) {
        sC[tid]       = b1[tid];
        sC[128 + tid] = b2[tid];
        sC[256 + tid] = W3[tid];
        sC[384 + tid] = W1[tid];            // W1 row 0 (conn column)
    }
    float b3v = __ldg(b3);
    float ikT = 1.0f / __ldg(kT);

    // ---- connectivity: stable per-graph degree rank (2 graphs) ----
    int* sDeg = reinterpret_cast<int*>(sH);
    if (tid < 128) sDeg[tid] = g_deg[row0 + tid];
    __syncthreads();
    if (tid < 128) {
        int gg = tid >> 6;                  // 0 or 1
        int li = tid & 63;
        int base = gg * 64;
        int di = sDeg[tid];
        int r = 0;
#pragma unroll 8
        for (int j = 0; j < GSIZE; ++j) {
            int dj = sDeg[base + j];
            r += (dj < di) || (dj == di && j < li);
        }
        sConn[base + r] = (float)li * (1.0f / 64.0f);
    }
    __syncthreads();

    // ---- GEMM1 acc init: conn column + bias ----
    unsigned long long acc[8][4];
    {
        float cr[8];
#pragma unroll
        for (int i = 0; i < 8; ++i) cr[i] = sConn[ty * 8 + i];
#pragma unroll
        for (int jp = 0; jp < 4; ++jp) {
            int c = tx * 8 + 2 * jp;
            float wa = sC[384 + c], wb = sC[384 + c + 1];
            float ba = sC[c],       bb = sC[c + 1];
#pragma unroll
            for (int i = 0; i < 8; ++i)
                acc[i][jp] = pack2(fmaf(cr[i], wa, ba), fmaf(cr[i], wb, bb));
        }
    }

    // per-thread staging indices
    const int am = tid >> 3;                // A: row 0..127 (stride 32 over p)
    const int ak = tid & 7;                 // A: k4 group
    const int bk = tid >> 5;                // B: k row (stride 8 over p)
    const int bn = tid & 31;                // B: float4 col

    // ---- GEMM1: [conn|X] @ W1, K=257 over 8 chunks of 32, prefetched ----
    float4 pa[4], pb[4];
#pragma unroll
    for (int p = 0; p < 4; ++p) {
        pa[p] = *reinterpret_cast<const float4*>(
            X + (size_t)(row0 + am + 32 * p) * HID + 4 * ak);
        pb[p] = *reinterpret_cast<const float4*>(
            W1 + (size_t)(1 + bk + 8 * p) * NH1 + 4 * bn);
    }
    for (int kc = 0; kc < 8; ++kc) {
        __syncthreads();                    // previous inner done
#pragma unroll
        for (int p = 0; p < 4; ++p) {
            int m = am + 32 * p;
            sA[(4 * ak + 0) * APITCH + m] = pa[p].x;
            sA[(4 * ak + 1) * APITCH + m] = pa[p].y;
            sA[(4 * ak + 2) * APITCH + m] = pa[p].z;
            sA[(4 * ak + 3) * APITCH + m] = pa[p].w;
            *reinterpret_cast<float4*>(sB + (bk + 8 * p) * BPITCH + 4 * bn) = pb[p];
        }
        __syncthreads();
        if (kc < 7) {
            int f0 = (kc + 1) * 32;
#pragma unroll
            for (int p = 0; p < 4; ++p) {
                pa[p] = *reinterpret_cast<const float4*>(
                    X + (size_t)(row0 + am + 32 * p) * HID + f0 + 4 * ak);
                pb[p] = *reinterpret_cast<const float4*>(
                    W1 + (size_t)(1 + f0 + bk + 8 * p) * NH1 + 4 * bn);
            }
        }
        gemm_inner(sA, sB, tx, ty, acc);
    }

    // ---- GEMM1 epilogue: silu -> sH (row-major) ----
#pragma unroll
    for (int i = 0; i < 8; ++i) {
        int row = ty * 8 + i;
#pragma unroll
        for (int jp = 0; jp < 4; ++jp) {
            float2 v = unpack2(acc[i][jp]);
            int col = tx * 8 + 2 * jp;
            sH[row * HPITCH + col]     = silu(v.x);
            sH[row * HPITCH + col + 1] = silu(v.y);
        }
    }

    // ---- GEMM2 acc init: bias b2 ----
#pragma unroll
    for (int jp = 0; jp < 4; ++jp) {
        int c = tx * 8 + 2 * jp;
        unsigned long long binit = pack2(sC[128 + c], sC[128 + c + 1]);
#pragma unroll
        for (int i = 0; i < 8; ++i) acc[i][jp] = binit;
    }

    // ---- GEMM2: H1 @ W2, K=128 over 4 chunks; A staged from sH ----
#pragma unroll
    for (int p = 0; p < 4; ++p)
        pb[p] = *reinterpret_cast<const float4*>(
            W2 + (size_t)(bk + 8 * p) * NH1 + 4 * bn);

    for (int kc = 0; kc < 4; ++kc) {
        int k0 = kc * 32;
        __syncthreads();                    // prev inner done; sH visible
#pragma unroll
        for (int p = 0; p < 4; ++p) {
            int m = am + 32 * p;
            float4 h4 = *reinterpret_cast<const float4*>(sH + m * HPITCH + k0 + 4 * ak);
            sA[(4 * ak + 0) * APITCH + m] = h4.x;
            sA[(4 * ak + 1) * APITCH + m] = h4.y;
            sA[(4 * ak + 2) * APITCH + m] = h4.z;
            sA[(4 * ak + 3) * APITCH + m] = h4.w;
            *reinterpret_cast<float4*>(sB + (bk + 8 * p) * BPITCH + 4 * bn) = pb[p];
        }
        __syncthreads();
        if (kc < 3) {
            int k1 = (kc + 1) * 32;
#pragma unroll
            for (int p = 0; p < 4; ++p)
                pb[p] = *reinterpret_cast<const float4*>(
                    W2 + (size_t)(k1 + bk + 8 * p) * NH1 + 4 * bn);
        }
        gemm_inner(sA, sB, tx, ty, acc);
    }

    // ---- layer 3 partials: silu(H2pre) . W3 ----
    float part[8];
#pragma unroll
    for (int i = 0; i < 8; ++i) {
        float s = 0.0f;
#pragma unroll
        for (int jp = 0; jp < 4; ++jp) {
            float2 v = unpack2(acc[i][jp]);
            int col = tx * 8 + 2 * jp;
            s = fmaf(silu(v.x), sC[256 + col], s);
            s = fmaf(silu(v.y), sC[256 + col + 1], s);
        }
        part[i] = s;
    }
    __syncthreads();                        // inner done; sA reusable
    float* sPart = reinterpret_cast<float*>(smem);   // [128][17] over sA
#pragma unroll
    for (int i = 0; i < 8; ++i) sPart[(ty * 8 + i) * 17 + tx] = part[i];
    __syncthreads();

    if (tid < 128) {
        float s = 0.0f;
#pragma unroll
        for (int t = 0; t < 16; ++t) s += sPart[tid * 17 + t];
        sLog[tid] = (s + b3v) * ikT;
    }
    __syncthreads();

    // ---- per-graph softmax: warp 0 -> graph 0, warp 1 -> graph 1 ----
    if (tid < 64) {
        int w    = tid >> 5;
        int lane = tid & 31;
        int base = w * 64;
        float a  = sLog[base + lane];
        float b  = sLog[base + lane + 32];
        float mx = fmaxf(a, b);
#pragma unroll
        for (int o = 16; o; o >>= 1) mx = fmaxf(mx, __shfl_xor_sync(0xffffffffu, mx, o));
        float e0 = expf(a - mx);
        float e1 = expf(b - mx);
        float s  = e0 + e1;
#pragma unroll
        for (int o = 16; o; o >>= 1) s += __shfl_xor_sync(0xffffffffu, s, o);
        float inv = 1.0f / s;
        out[row0 + base + lane]      = e0 * inv;
        out[row0 + base + lane + 32] = e1 * inv;
    }
}

// ---------------- launcher ----------------
extern "C" void kernel_launch(void* const* d_in, const int* in_sizes, int n_in,
                              void* d_out, int out_size) {
    const float* X  = (const float*)d_in[0];
    const float* W1 = (const float*)d_in[1];
    const float* b1 = (const float*)d_in[2];
    const float* W2 = (const float*)d_in[3];
    const float* b2 = (const float*)d_in[4];
    const float* W3 = (const float*)d_in[5];
    const float* b3 = (const float*)d_in[6];
    const float* kT = (const float*)d_in[7];
    const int*   ei = (const int*)d_in[8];
    float* out = (float*)d_out;

    void* degPtr = nullptr;
    cudaGetSymbolAddress(&degPtr, g_deg);
    cudaMemsetAsync(degPtr, 0, NUM_NODES * sizeof(int));

    deg_kernel<<<EDGES / 4 / 256, 256>>>(ei);

    cudaFuncSetAttribute(mlp_kernel, cudaFuncAttributeMaxDynamicSharedMemorySize,
                         SMEM_BYTES);
    mlp_kernel<<<NGRAPH / 2, 256, SMEM_BYTES>>>(X, W1, b1, W2, b2, W3, b3, kT, out);
}

// round 6
// speedup vs baseline: 2.5838x; 2.5798x over previous
#include <cuda_runtime.h>
#include <cstdint>

#define NUM_NODES 65536
#define NGRAPH    1024
#define GSIZE     64
#define HID       256
#define NH1       128
#define EDGES     2097152

// ---------------- scratch ----------------
__device__ int g_deg[NUM_NODES];

// ---------------- degree histogram ----------------
__global__ void deg_kernel(const int* __restrict__ src) {
    int i = blockIdx.x * blockDim.x + threadIdx.x;
    int4 v = reinterpret_cast<const int4*>(src)[i];
    atomicAdd(&g_deg[v.x], 1);
    atomicAdd(&g_deg[v.y], 1);
    atomicAdd(&g_deg[v.z], 1);
    atomicAdd(&g_deg[v.w], 1);
}

// ---------------- mma.sync m16n8k8 tf32 ----------------
__device__ __forceinline__ void mma_tf32(float d[4], const uint32_t a[4],
                                         const uint32_t b[2]) {
    asm volatile(
        "mma.sync.aligned.m16n8k8.row.col.f32.tf32.tf32.f32 "
        "{%0,%1,%2,%3}, {%4,%5,%6,%7}, {%8,%9}, {%0,%1,%2,%3};"
        : "+f"(d[0]), "+f"(d[1]), "+f"(d[2]), "+f"(d[3])
        : "r"(a[0]), "r"(a[1]), "r"(a[2]), "r"(a[3]), "r"(b[0]), "r"(b[1]));
}

__device__ __forceinline__ float silu(float x) { return x / (1.0f + __expf(-x)); }

// ---------------- smem layout (float offsets where noted) ----------------
// A chunk : [128][68]  f32 @ 0       (34816 B)   pitch 68  (68%32==4 -> cf)
// B chunk : [64][136]  f32 @ 34816   (34816 B)   pitch 136 (136%32==8 -> cf)
// H       : [128][132] f32 @ 0       (67584 B)   overlays A+B after GEMM1
// W2 chunk: [64][136]  f32 @ 69632   (34816 B)
// sC      : 512 f32    @ 104448     b1 | b2 | W3 | W1row0
// sConn   : 128 f32    @ 106496
// sLog    : 128 f32    @ 107008
// sRed    : 1024 f32   @ 107520     [128][8] partials (also sDeg early)
#define OFF_A    0
#define OFF_B    34816
#define OFF_H    0
#define OFF_W2   69632
#define OFF_C    104448
#define OFF_CONN 106496
#define OFF_LOG  107008
#define OFF_RED  107520
#define SMEM_BYTES 111616

#define APITCH 68
#define BPITCH 136
#define HPITCH 132

__global__ void __launch_bounds__(256, 2)
mlp_kernel(const float* __restrict__ X,  const float* __restrict__ W1,
           const float* __restrict__ b1, const float* __restrict__ W2,
           const float* __restrict__ b2, const float* __restrict__ W3,
           const float* __restrict__ b3, const float* __restrict__ kT,
           float* __restrict__ out) {
    extern __shared__ char smem[];
    float* sA    = reinterpret_cast<float*>(smem + OFF_A);
    float* sB    = reinterpret_cast<float*>(smem + OFF_B);
    float* sH    = reinterpret_cast<float*>(smem + OFF_H);
    float* sW2   = reinterpret_cast<float*>(smem + OFF_W2);
    float* sC    = reinterpret_cast<float*>(smem + OFF_C);
    float* sConn = reinterpret_cast<float*>(smem + OFF_CONN);
    float* sLog  = reinterpret_cast<float*>(smem + OFF_LOG);
    float* sRed  = reinterpret_cast<float*>(smem + OFF_RED);

    const int tid  = threadIdx.x;                 // 256 threads, 8 warps
    const int wid  = tid >> 5;
    const int lane = tid & 31;
    const int la   = lane >> 2;                   // 0..7
    const int lb   = lane & 3;                    // 0..3
    const int wm   = wid & 3;                     // M block (32 rows)
    const int wn   = wid >> 2;                    // N block (64 cols)
    const int row0 = blockIdx.x * 128;            // 2 graphs per CTA

    // ---- constants ----
    if (tid < 128) {
        sC[tid]       = b1[tid];
        sC[128 + tid] = b2[tid];
        sC[256 + tid] = W3[tid];
        sC[384 + tid] = W1[tid];                  // W1 row 0 (conn column)
    }
    float b3v = __ldg(b3);
    float ikT = 1.0f / __ldg(kT);

    // ---- connectivity: stable per-graph degree rank (2 graphs) ----
    int* sDeg = reinterpret_cast<int*>(sRed);
    if (tid < 128) sDeg[tid] = g_deg[row0 + tid];
    __syncthreads();
    if (tid < 128) {
        int gg = tid >> 6, li = tid & 63, base = gg * 64;
        int di = sDeg[tid], r = 0;
#pragma unroll 8
        for (int j = 0; j < GSIZE; ++j) {
            int dj = sDeg[base + j];
            r += (dj < di) || (dj == di && j < li);
        }
        sConn[base + r] = (float)li * (1.0f / 64.0f);
    }
    __syncthreads();

    // ---- GEMM1 acc init: b1[n] + conn[m] * W1row0[n] ----
    float acc[2][8][4];
    {
        float cn[2][2];
#pragma unroll
        for (int mt = 0; mt < 2; ++mt) {
            cn[mt][0] = sConn[wm * 32 + mt * 16 + la];
            cn[mt][1] = sConn[wm * 32 + mt * 16 + 8 + la];
        }
#pragma unroll
        for (int nt = 0; nt < 8; ++nt) {
            int n0 = wn * 64 + nt * 8 + 2 * lb;
            float w0 = sC[384 + n0], w1 = sC[384 + n0 + 1];
            float bb0 = sC[n0],      bb1 = sC[n0 + 1];
#pragma unroll
            for (int mt = 0; mt < 2; ++mt) {
                acc[mt][nt][0] = fmaf(cn[mt][0], w0, bb0);
                acc[mt][nt][1] = fmaf(cn[mt][0], w1, bb1);
                acc[mt][nt][2] = fmaf(cn[mt][1], w0, bb0);
                acc[mt][nt][3] = fmaf(cn[mt][1], w1, bb1);
            }
        }
    }

    const uint32_t* Au = reinterpret_cast<const uint32_t*>(sA);
    const uint32_t* Bu = reinterpret_cast<const uint32_t*>(sB);

    // ---- GEMM1: [conn|X] @ W1, K=256 in 4 chunks of 64 ----
    for (int c = 0; c < 4; ++c) {
        __syncthreads();                          // prev chunk mma done
        // stage A: X[128 x 64] row-major pitch 68
#pragma unroll
        for (int p = 0; p < 8; ++p) {
            int idx = tid + 256 * p;              // 0..2047
            int m = idx >> 4, kq = idx & 15;
            float4 x4 = *reinterpret_cast<const float4*>(
                X + (size_t)(row0 + m) * HID + c * 64 + 4 * kq);
            *reinterpret_cast<float4*>(sA + m * APITCH + 4 * kq) = x4;
        }
        // stage B: W1 rows [1+c*64, 1+c*64+64), pitch 136
#pragma unroll
        for (int p = 0; p < 8; ++p) {
            int idx = tid + 256 * p;
            int k = idx >> 5, nq = idx & 31;
            float4 w = *reinterpret_cast<const float4*>(
                W1 + (size_t)(1 + c * 64 + k) * NH1 + 4 * nq);
            *reinterpret_cast<float4*>(sB + k * BPITCH + 4 * nq) = w;
        }
        __syncthreads();
#pragma unroll
        for (int kt = 0; kt < 8; ++kt) {
            int k0 = kt * 8;
            uint32_t a[2][4];
#pragma unroll
            for (int mt = 0; mt < 2; ++mt) {
                int m0 = wm * 32 + mt * 16;
                a[mt][0] = Au[(m0 + la) * APITCH + k0 + lb];
                a[mt][1] = Au[(m0 + 8 + la) * APITCH + k0 + lb];
                a[mt][2] = Au[(m0 + la) * APITCH + k0 + 4 + lb];
                a[mt][3] = Au[(m0 + 8 + la) * APITCH + k0 + 4 + lb];
            }
#pragma unroll
            for (int nt = 0; nt < 8; ++nt) {
                int n0 = wn * 64 + nt * 8;
                uint32_t b[2];
                b[0] = Bu[(k0 + lb) * BPITCH + n0 + la];
                b[1] = Bu[(k0 + 4 + lb) * BPITCH + n0 + la];
                mma_tf32(acc[0][nt], a[0], b);
                mma_tf32(acc[1][nt], a[1], b);
            }
        }
    }
    __syncthreads();                              // all warps done reading A/B

    // ---- epilogue1: silu -> sH (overlays A/B) ----
#pragma unroll
    for (int mt = 0; mt < 2; ++mt) {
        int m0 = wm * 32 + mt * 16 + la;
#pragma unroll
        for (int nt = 0; nt < 8; ++nt) {
            int n0 = wn * 64 + nt * 8 + 2 * lb;
            float2 v0 = make_float2(silu(acc[mt][nt][0]), silu(acc[mt][nt][1]));
            float2 v1 = make_float2(silu(acc[mt][nt][2]), silu(acc[mt][nt][3]));
            *reinterpret_cast<float2*>(sH + m0 * HPITCH + n0)       = v0;
            *reinterpret_cast<float2*>(sH + (m0 + 8) * HPITCH + n0) = v1;
        }
    }

    // ---- GEMM2 acc init: b2[n] ----
#pragma unroll
    for (int nt = 0; nt < 8; ++nt) {
        int n0 = wn * 64 + nt * 8 + 2 * lb;
        float bb0 = sC[128 + n0], bb1 = sC[128 + n0 + 1];
#pragma unroll
        for (int mt = 0; mt < 2; ++mt) {
            acc[mt][nt][0] = bb0; acc[mt][nt][1] = bb1;
            acc[mt][nt][2] = bb0; acc[mt][nt][3] = bb1;
        }
    }

    const uint32_t* Hu  = reinterpret_cast<const uint32_t*>(sH);
    const uint32_t* W2u = reinterpret_cast<const uint32_t*>(sW2);

    // ---- GEMM2: H1 @ W2, K=128 in 2 chunks of 64 ----
    for (int c = 0; c < 2; ++c) {
        __syncthreads();                          // H ready / prev chunk done
#pragma unroll
        for (int p = 0; p < 8; ++p) {
            int idx = tid + 256 * p;
            int k = idx >> 5, nq = idx & 31;
            float4 w = *reinterpret_cast<const float4*>(
                W2 + (size_t)(c * 64 + k) * NH1 + 4 * nq);
            *reinterpret_cast<float4*>(sW2 + k * BPITCH + 4 * nq) = w;
        }
        __syncthreads();
#pragma unroll
        for (int kt = 0; kt < 8; ++kt) {
            int k0 = kt * 8;                      // within chunk
            int kg = c * 64 + k0;                 // global H col
            uint32_t a[2][4];
#pragma unroll
            for (int mt = 0; mt < 2; ++mt) {
                int m0 = wm * 32 + mt * 16;
                a[mt][0] = Hu[(m0 + la) * HPITCH + kg + lb];
                a[mt][1] = Hu[(m0 + 8 + la) * HPITCH + kg + lb];
                a[mt][2] = Hu[(m0 + la) * HPITCH + kg + 4 + lb];
                a[mt][3] = Hu[(m0 + 8 + la) * HPITCH + kg + 4 + lb];
            }
#pragma unroll
            for (int nt = 0; nt < 8; ++nt) {
                int n0 = wn * 64 + nt * 8;
                uint32_t b[2];
                b[0] = W2u[(k0 + lb) * BPITCH + n0 + la];
                b[1] = W2u[(k0 + 4 + lb) * BPITCH + n0 + la];
                mma_tf32(acc[0][nt], a[0], b);
                mma_tf32(acc[1][nt], a[1], b);
            }
        }
    }
    __syncthreads();

    // ---- epilogue2: silu(D2) . W3 -> per-lane partials -> sRed ----
#pragma unroll
    for (int mt = 0; mt < 2; ++mt) {
#pragma unroll
        for (int half = 0; half < 2; ++half) {
            float p = 0.0f;
#pragma unroll
            for (int nt = 0; nt < 8; ++nt) {
                int n0 = wn * 64 + nt * 8 + 2 * lb;
                float v0 = acc[mt][nt][half * 2 + 0];
                float v1 = acc[mt][nt][half * 2 + 1];
                p = fmaf(silu(v0), sC[256 + n0], p);
                p = fmaf(silu(v1), sC[256 + n0 + 1], p);
            }
            int m = wm * 32 + mt * 16 + half * 8 + la;
            sRed[m * 8 + lb + 4 * wn] = p;
        }
    }
    __syncthreads();

    if (tid < 128) {
        float s = 0.0f;
#pragma unroll
        for (int t = 0; t < 8; ++t) s += sRed[tid * 8 + t];
        sLog[tid] = (s + b3v) * ikT;
    }
    __syncthreads();

    // ---- per-graph softmax: warp 0 -> graph 0, warp 1 -> graph 1 ----
    if (tid < 64) {
        int w = tid >> 5, l = tid & 31, base = w * 64;
        float a  = sLog[base + l];
        float b  = sLog[base + l + 32];
        float mx = fmaxf(a, b);
#pragma unroll
        for (int o = 16; o; o >>= 1) mx = fmaxf(mx, __shfl_xor_sync(0xffffffffu, mx, o));
        float e0 = expf(a - mx), e1 = expf(b - mx);
        float s = e0 + e1;
#pragma unroll
        for (int o = 16; o; o >>= 1) s += __shfl_xor_sync(0xffffffffu, s, o);
        float inv = 1.0f / s;
        out[row0 + base + l]      = e0 * inv;
        out[row0 + base + l + 32] = e1 * inv;
    }
}

// ---------------- launcher ----------------
extern "C" void kernel_launch(void* const* d_in, const int* in_sizes, int n_in,
                              void* d_out, int out_size) {
    const float* X  = (const float*)d_in[0];
    const float* W1 = (const float*)d_in[1];
    const float* b1 = (const float*)d_in[2];
    const float* W2 = (const float*)d_in[3];
    const float* b2 = (const float*)d_in[4];
    const float* W3 = (const float*)d_in[5];
    const float* b3 = (const float*)d_in[6];
    const float* kT = (const float*)d_in[7];
    const int*   ei = (const int*)d_in[8];
    float* out = (float*)d_out;

    void* degPtr = nullptr;
    cudaGetSymbolAddress(&degPtr, g_deg);
    cudaMemsetAsync(degPtr, 0, NUM_NODES * sizeof(int));

    deg_kernel<<<EDGES / 4 / 256, 256>>>(ei);

    cudaFuncSetAttribute(mlp_kernel, cudaFuncAttributeMaxDynamicSharedMemorySize,
                         SMEM_BYTES);
    mlp_kernel<<<NGRAPH / 2, 256, SMEM_BYTES>>>(X, W1, b1, W2, b2, W3, b3, kT, out);
}

// round 7
// speedup vs baseline: 2.8759x; 1.1130x over previous
#include <cuda_runtime.h>
#include <cstdint>

#define NUM_NODES 65536
#define NGRAPH    1024
#define GSIZE     64
#define HID       256
#define NH1       128
#define EDGES     2097152

// ---------------- scratch ----------------
__device__ int g_deg[NUM_NODES];

// ---------------- degree histogram ----------------
__global__ void deg_kernel(const int* __restrict__ src) {
    int i = blockIdx.x * blockDim.x + threadIdx.x;
    int4 v = reinterpret_cast<const int4*>(src)[i];
    atomicAdd(&g_deg[v.x], 1);
    atomicAdd(&g_deg[v.y], 1);
    atomicAdd(&g_deg[v.z], 1);
    atomicAdd(&g_deg[v.w], 1);
}

// ---------------- mma.sync m16n8k8 tf32 ----------------
__device__ __forceinline__ void mma_tf32(float d[4], const uint32_t a[4],
                                         const uint32_t b[2]) {
    asm volatile(
        "mma.sync.aligned.m16n8k8.row.col.f32.tf32.tf32.f32 "
        "{%0,%1,%2,%3}, {%4,%5,%6,%7}, {%8,%9}, {%0,%1,%2,%3};"
        : "+f"(d[0]), "+f"(d[1]), "+f"(d[2]), "+f"(d[3])
        : "r"(a[0]), "r"(a[1]), "r"(a[2]), "r"(a[3]), "r"(b[0]), "r"(b[1]));
}

__device__ __forceinline__ uint32_t smem_u32(const void* p) {
    uint32_t a;
    asm("{ .reg .u64 t; cvta.to.shared.u64 t, %1; cvt.u32.u64 %0, t; }"
        : "=r"(a) : "l"(p));
    return a;
}
#define CP16(dst, src) \
    asm volatile("cp.async.cg.shared.global [%0], [%1], 16;" \
                 :: "r"(dst), "l"(src) : "memory")
#define CPCOMMIT() asm volatile("cp.async.commit_group;" ::: "memory")
#define CPWAIT(n)  asm volatile("cp.async.wait_group %0;" :: "n"(n) : "memory")

__device__ __forceinline__ float silu(float x) { return x / (1.0f + __expf(-x)); }

// ---------------- smem layout (bytes) ----------------
// A ring : 3 x [128][36] f32 = 3 x 18432 @ 0        (55296)
// B ring : 3 x [32][136] f32 = 3 x 17408 @ 55296    (52224)  end 107520
// H      : [128][132] f32 @ 0 (67584)   overlays A ring + B0 (after GEMM1)
// W2 bufs: 2 x [32][136] @ 72704 (B1/B2 region)     end 107520
// sC     : 512 f32 @ 107520   b1 | b2 | W3 | W1row0
// sConn  : 128 f32 @ 109568
// sLog   : 128 f32 @ 110080
// sRed   : 1024 f32 @ 110592  (also sDeg early)
#define RA(i)     ((i) * 18432)
#define RB(i)     (55296 + (i) * 17408)
#define OFF_H     0
#define OFF_W2(i) (72704 + (i) * 17408)
#define OFF_C     107520
#define OFF_CONN  109568
#define OFF_LOG   110080
#define OFF_RED   110592
#define SMEM_BYTES 114688

#define APITCH 36     /* 36 % 32 == 4 -> conflict-free A frag loads */
#define BPITCH 136    /* 136 % 32 == 8 -> conflict-free B frag loads */
#define HPITCH 132

__global__ void __launch_bounds__(256, 2)
mlp_kernel(const float* __restrict__ X,  const float* __restrict__ W1,
           const float* __restrict__ b1, const float* __restrict__ W2,
           const float* __restrict__ b2, const float* __restrict__ W3,
           const float* __restrict__ b3, const float* __restrict__ kT,
           float* __restrict__ out) {
    extern __shared__ char smem[];
    const uint32_t sb = smem_u32(smem);
    float* sC    = reinterpret_cast<float*>(smem + OFF_C);
    float* sConn = reinterpret_cast<float*>(smem + OFF_CONN);
    float* sLog  = reinterpret_cast<float*>(smem + OFF_LOG);
    float* sRed  = reinterpret_cast<float*>(smem + OFF_RED);

    const int tid  = threadIdx.x;                 // 256 threads, 8 warps
    const int wid  = tid >> 5;
    const int lane = tid & 31;
    const int la   = lane >> 2;                   // 0..7
    const int lb   = lane & 3;                    // 0..3
    const int wm   = wid & 3;                     // M block (32 rows)
    const int wn   = wid >> 2;                    // N block (64 cols)
    const int row0 = blockIdx.x * 128;            // 2 graphs per CTA

    // ---- staging helpers (cp.async, 8/4 x 16B per thread) ----
    auto stageAB = [&](int c, int ring) {
#pragma unroll
        for (int p = 0; p < 4; ++p) {
            int idx = tid + 256 * p;              // 0..1023
            int m = idx >> 3, kq = idx & 7;
            uint32_t dst = sb + RA(ring) + (uint32_t)(m * APITCH + 4 * kq) * 4u;
            const float* src = X + (size_t)(row0 + m) * HID + c * 32 + 4 * kq;
            CP16(dst, src);
        }
#pragma unroll
        for (int p = 0; p < 4; ++p) {
            int idx = tid + 256 * p;
            int k = idx >> 5, nq = idx & 31;
            uint32_t dst = sb + RB(ring) + (uint32_t)(k * BPITCH + 4 * nq) * 4u;
            const float* src = W1 + (size_t)(1 + c * 32 + k) * NH1 + 4 * nq;
            CP16(dst, src);
        }
        CPCOMMIT();
    };
    auto stageW2 = [&](int c, int bi) {
#pragma unroll
        for (int p = 0; p < 4; ++p) {
            int idx = tid + 256 * p;
            int k = idx >> 5, nq = idx & 31;
            uint32_t dst = sb + OFF_W2(bi) + (uint32_t)(k * BPITCH + 4 * nq) * 4u;
            const float* src = W2 + (size_t)(c * 32 + k) * NH1 + 4 * nq;
            CP16(dst, src);
        }
        CPCOMMIT();
    };

    // ---- constants + degrees ----
    if (tid < 128) {
        sC[tid]       = b1[tid];
        sC[128 + tid] = b2[tid];
        sC[256 + tid] = W3[tid];
        sC[384 + tid] = W1[tid];                  // W1 row 0 (conn column)
    }
    float b3v = __ldg(b3);
    float ikT = 1.0f / __ldg(kT);
    int* sDeg = reinterpret_cast<int*>(sRed);
    if (tid < 128) sDeg[tid] = g_deg[row0 + tid];
    __syncthreads();                              // sDeg visible

    // kick pipeline: chunks 0,1 in flight while we compute ranks
    stageAB(0, 0);
    stageAB(1, 1);

    // ---- connectivity: stable per-graph degree rank (2 graphs) ----
    if (tid < 128) {
        int gg = tid >> 6, li = tid & 63, base = gg * 64;
        int di = sDeg[tid], rk = 0;
#pragma unroll 8
        for (int j = 0; j < GSIZE; ++j) {
            int dj = sDeg[base + j];
            rk += (dj < di) || (dj == di && j < li);
        }
        sConn[base + rk] = (float)li * (1.0f / 64.0f);
    }
    __syncthreads();                              // sConn visible

    // ---- GEMM1 acc init: b1[n] + conn[m] * W1row0[n] ----
    float acc[2][8][4];
    {
        float cn[2][2];
#pragma unroll
        for (int mt = 0; mt < 2; ++mt) {
            cn[mt][0] = sConn[wm * 32 + mt * 16 + la];
            cn[mt][1] = sConn[wm * 32 + mt * 16 + 8 + la];
        }
#pragma unroll
        for (int nt = 0; nt < 8; ++nt) {
            int n0 = wn * 64 + nt * 8 + 2 * lb;
            float w0 = sC[384 + n0], w1 = sC[384 + n0 + 1];
            float bb0 = sC[n0],      bb1 = sC[n0 + 1];
#pragma unroll
            for (int mt = 0; mt < 2; ++mt) {
                acc[mt][nt][0] = fmaf(cn[mt][0], w0, bb0);
                acc[mt][nt][1] = fmaf(cn[mt][0], w1, bb1);
                acc[mt][nt][2] = fmaf(cn[mt][1], w0, bb0);
                acc[mt][nt][3] = fmaf(cn[mt][1], w1, bb1);
            }
        }
    }

    // ---- GEMM1: [conn|X] @ W1, K=256 in 8 chunks of 32, 3-stage ring ----
#pragma unroll
    for (int c = 0; c < 8; ++c) {
        if (c < 7) { CPWAIT(1); } else { CPWAIT(0); }
        __syncthreads();                          // chunk c ready; MMA(c-1) done by all
        if (c < 6) stageAB(c + 2, (c + 2) % 3);   // overwrite ring last read at MMA(c-1)
        const uint32_t* Au = reinterpret_cast<const uint32_t*>(smem + RA(c % 3));
        const uint32_t* Bu = reinterpret_cast<const uint32_t*>(smem + RB(c % 3));
#pragma unroll
        for (int kt = 0; kt < 4; ++kt) {
            int k0 = kt * 8;
            uint32_t a[2][4];
#pragma unroll
            for (int mt = 0; mt < 2; ++mt) {
                int m0 = wm * 32 + mt * 16;
                a[mt][0] = Au[(m0 + la) * APITCH + k0 + lb];
                a[mt][1] = Au[(m0 + 8 + la) * APITCH + k0 + lb];
                a[mt][2] = Au[(m0 + la) * APITCH + k0 + 4 + lb];
                a[mt][3] = Au[(m0 + 8 + la) * APITCH + k0 + 4 + lb];
            }
#pragma unroll
            for (int nt = 0; nt < 8; ++nt) {
                int n0 = wn * 64 + nt * 8;
                uint32_t b[2];
                b[0] = Bu[(k0 + lb) * BPITCH + n0 + la];
                b[1] = Bu[(k0 + 4 + lb) * BPITCH + n0 + la];
                mma_tf32(acc[0][nt], a[0], b);
                mma_tf32(acc[1][nt], a[1], b);
            }
        }
    }
    __syncthreads();                              // all MMA(7) done before H/W2 writes

    // W2 chunks 0,1 in flight while epilogue1 runs
    stageW2(0, 0);
    stageW2(1, 1);

    // ---- epilogue1: silu -> sH (overlays A ring + B0) ----
    float* sH = reinterpret_cast<float*>(smem + OFF_H);
#pragma unroll
    for (int mt = 0; mt < 2; ++mt) {
        int m0 = wm * 32 + mt * 16 + la;
#pragma unroll
        for (int nt = 0; nt < 8; ++nt) {
            int n0 = wn * 64 + nt * 8 + 2 * lb;
            float2 v0 = make_float2(silu(acc[mt][nt][0]), silu(acc[mt][nt][1]));
            float2 v1 = make_float2(silu(acc[mt][nt][2]), silu(acc[mt][nt][3]));
            *reinterpret_cast<float2*>(sH + m0 * HPITCH + n0)       = v0;
            *reinterpret_cast<float2*>(sH + (m0 + 8) * HPITCH + n0) = v1;
        }
    }

    // ---- GEMM2 acc init: b2[n] ----
#pragma unroll
    for (int nt = 0; nt < 8; ++nt) {
        int n0 = wn * 64 + nt * 8 + 2 * lb;
        float bb0 = sC[128 + n0], bb1 = sC[128 + n0 + 1];
#pragma unroll
        for (int mt = 0; mt < 2; ++mt) {
            acc[mt][nt][0] = bb0; acc[mt][nt][1] = bb1;
            acc[mt][nt][2] = bb0; acc[mt][nt][3] = bb1;
        }
    }

    const uint32_t* Hu = reinterpret_cast<const uint32_t*>(sH);

    // ---- GEMM2: H1 @ W2, K=128 in 4 chunks of 32, double-buffered ----
#pragma unroll
    for (int c = 0; c < 4; ++c) {
        if (c == 0) { CPWAIT(1); } else { CPWAIT(0); }
        __syncthreads();                          // data ready; H visible; prev MMA done
        if (c == 1) stageW2(2, 0);                // wbuf0 freed by MMA2(0)
        if (c == 2) stageW2(3, 1);                // wbuf1 freed by MMA2(1)
        const uint32_t* W2u = reinterpret_cast<const uint32_t*>(smem + OFF_W2(c & 1));
#pragma unroll
        for (int kt = 0; kt < 4; ++kt) {
            int k0 = kt * 8;                      // within chunk
            int kg = c * 32 + k0;                 // global H col
            uint32_t a[2][4];
#pragma unroll
            for (int mt = 0; mt < 2; ++mt) {
                int m0 = wm * 32 + mt * 16;
                a[mt][0] = Hu[(m0 + la) * HPITCH + kg + lb];
                a[mt][1] = Hu[(m0 + 8 + la) * HPITCH + kg + lb];
                a[mt][2] = Hu[(m0 + la) * HPITCH + kg + 4 + lb];
                a[mt][3] = Hu[(m0 + 8 + la) * HPITCH + kg + 4 + lb];
            }
#pragma unroll
            for (int nt = 0; nt < 8; ++nt) {
                int n0 = wn * 64 + nt * 8;
                uint32_t b[2];
                b[0] = W2u[(k0 + lb) * BPITCH + n0 + la];
                b[1] = W2u[(k0 + 4 + lb) * BPITCH + n0 + la];
                mma_tf32(acc[0][nt], a[0], b);
                mma_tf32(acc[1][nt], a[1], b);
            }
        }
    }
    __syncthreads();

    // ---- epilogue2: silu(D2) . W3 -> partials -> sRed ----
#pragma unroll
    for (int mt = 0; mt < 2; ++mt) {
#pragma unroll
        for (int half = 0; half < 2; ++half) {
            float p = 0.0f;
#pragma unroll
            for (int nt = 0; nt < 8; ++nt) {
                int n0 = wn * 64 + nt * 8 + 2 * lb;
                float v0 = acc[mt][nt][half * 2 + 0];
                float v1 = acc[mt][nt][half * 2 + 1];
                p = fmaf(silu(v0), sC[256 + n0], p);
                p = fmaf(silu(v1), sC[256 + n0 + 1], p);
            }
            int m = wm * 32 + mt * 16 + half * 8 + la;
            sRed[m * 8 + lb + 4 * wn] = p;
        }
    }
    __syncthreads();

    if (tid < 128) {
        float s = 0.0f;
#pragma unroll
        for (int t = 0; t < 8; ++t) s += sRed[tid * 8 + t];
        sLog[tid] = (s + b3v) * ikT;
    }
    __syncthreads();

    // ---- per-graph softmax: warp 0 -> graph 0, warp 1 -> graph 1 ----
    if (tid < 64) {
        int w = tid >> 5, l = tid & 31, base = w * 64;
        float a  = sLog[base + l];
        float b  = sLog[base + l + 32];
        float mx = fmaxf(a, b);
#pragma unroll
        for (int o = 16; o; o >>= 1) mx = fmaxf(mx, __shfl_xor_sync(0xffffffffu, mx, o));
        float e0 = expf(a - mx), e1 = expf(b - mx);
        float s = e0 + e1;
#pragma unroll
        for (int o = 16; o; o >>= 1) s += __shfl_xor_sync(0xffffffffu, s, o);
        float inv = 1.0f / s;
        out[row0 + base + l]      = e0 * inv;
        out[row0 + base + l + 32] = e1 * inv;
    }
}

// ---------------- launcher ----------------
extern "C" void kernel_launch(void* const* d_in, const int* in_sizes, int n_in,
                              void* d_out, int out_size) {
    const float* X  = (const float*)d_in[0];
    const float* W1 = (const float*)d_in[1];
    const float* b1 = (const float*)d_in[2];
    const float* W2 = (const float*)d_in[3];
    const float* b2 = (const float*)d_in[4];
    const float* W3 = (const float*)d_in[5];
    const float* b3 = (const float*)d_in[6];
    const float* kT = (const float*)d_in[7];
    const int*   ei = (const int*)d_in[8];
    float* out = (float*)d_out;

    void* degPtr = nullptr;
    cudaGetSymbolAddress(&degPtr, g_deg);
    cudaMemsetAsync(degPtr, 0, NUM_NODES * sizeof(int));

    deg_kernel<<<EDGES / 4 / 256, 256>>>(ei);

    cudaFuncSetAttribute(mlp_kernel, cudaFuncAttributeMaxDynamicSharedMemorySize,
                         SMEM_BYTES);
    mlp_kernel<<<NGRAPH / 2, 256, SMEM_BYTES>>>(X, W1, b1, W2, b2, W3, b3, kT, out);
}

// round 12
// speedup vs baseline: 3.1603x; 1.0989x over previous
#include <cuda_runtime.h>
#include <cuda_fp16.h>
#include <cstdint>

#define NUM_NODES 65536
#define NGRAPH    1024
#define GSIZE     64
#define HID       256
#define NH1       128
#define EDGES     2097152

// ---------------- scratch ----------------
__device__ int    g_deg[NUM_NODES];
__device__ __align__(16) __half g_w1h[NH1 * 256];   // W1 rows 1..256, transposed [n][k]
__device__ __align__(16) __half g_w2h[NH1 * NH1];   // W2 transposed [n][k]

// ---------------- pre-kernel: zero deg + convert/transpose weights ----------------
__global__ void conv_kernel(const float* __restrict__ W1,
                            const float* __restrict__ W2) {
    int t = blockIdx.x * blockDim.x + threadIdx.x;        // 32768 threads
    reinterpret_cast<int2*>(g_deg)[t] = make_int2(0, 0);
    {   // W1t: n = t&127, k = t>>7 (0..255); source row 1+k
        int n = t & 127, k = t >> 7;
        g_w1h[n * 256 + k] = __float2half_rn(W1[(1 + k) * NH1 + n]);
    }
    if (t < NH1 * NH1) {
        int n = t & 127, k = t >> 7;
        g_w2h[n * NH1 + k] = __float2half_rn(W2[k * NH1 + n]);
    }
}

// ---------------- degree histogram ----------------
__global__ void deg_kernel(const int* __restrict__ src) {
    int i = blockIdx.x * blockDim.x + threadIdx.x;
    int4 v = reinterpret_cast<const int4*>(src)[i];
    atomicAdd(&g_deg[v.x], 1);
    atomicAdd(&g_deg[v.y], 1);
    atomicAdd(&g_deg[v.z], 1);
    atomicAdd(&g_deg[v.w], 1);
}

// ---------------- mma.sync m16n8k16 f16 (fp32 accum) ----------------
__device__ __forceinline__ void mma16(float d[4], const uint32_t a[4],
                                      uint32_t b0, uint32_t b1) {
    asm volatile(
        "mma.sync.aligned.m16n8k16.row.col.f32.f16.f16.f32 "
        "{%0,%1,%2,%3}, {%4,%5,%6,%7}, {%8,%9}, {%0,%1,%2,%3};"
        : "+f"(d[0]), "+f"(d[1]), "+f"(d[2]), "+f"(d[3])
        : "r"(a[0]), "r"(a[1]), "r"(a[2]), "r"(a[3]), "r"(b0), "r"(b1));
}
// pack (lo, hi) -> f16x2 (round-to-nearest)
__device__ __forceinline__ uint32_t cvt2(float lo, float hi) {
    uint32_t r;
    asm("cvt.rn.f16x2.f32 %0, %1, %2;" : "=r"(r) : "f"(hi), "f"(lo));
    return r;
}
__device__ __forceinline__ uint32_t smem_u32(const void* p) {
    uint32_t a;
    asm("{ .reg .u64 t; cvta.to.shared.u64 t, %1; cvt.u32.u64 %0, t; }"
        : "=r"(a) : "l"(p));
    return a;
}
#define CP16(dst, src) \
    asm volatile("cp.async.cg.shared.global [%0], [%1], 16;" \
                 :: "r"(dst), "l"(src) : "memory")
#define CPCOMMIT() asm volatile("cp.async.commit_group;" ::: "memory")
#define CPWAIT(n)  asm volatile("cp.async.wait_group %0;" :: "n"(n) : "memory")

__device__ __forceinline__ float silu(float x) { return x / (1.0f + __expf(-x)); }

// ---------------- smem layout (bytes) ----------------
// A ring : 3 x [128 rows][36 f32]      = 3 x 18432 @ 0      (55296)
// B ring : 3 x [128 n][20 half2]       = 3 x 10240 @ 55296  (30720) end 86016
//          (GEMM2 W2 chunks reuse B bufs 0/1)
// H      : [128][68 half2] = 34816 @ 0   overlays A ring after GEMM1
// sC     : 512 f32 @ 86016  (b1 | b2 | W3 | W1row0)
// sConn  : 128 f32 @ 88064
// sLog   : 128 f32 @ 88576
// sRed   : 4096 B (1024 f32) @ 89088    end 93184
// sDeg   : 512 B   @ A-ring buf2 (RA(2)) -- free until chunk 2 staged
#define RA(i)     ((i) * 18432)
#define RB(i)     (55296 + (i) * 10240)
#define OFF_C     86016
#define OFF_CONN  88064
#define OFF_LOG   88576
#define OFF_RED   89088
#define SMEM_BYTES 93184

#define APITCH  36   /* f32,  36%32==4  -> conflict-light LDS.64 frag loads */
#define BPITCH2 20   /* half2, 20*la+lb distinct mod 32 -> conflict-free   */
#define HPITCH2 68   /* half2, 4*la+lb  distinct mod 32 -> conflict-free   */

__global__ void __launch_bounds__(256, 2)
mlp_kernel(const float* __restrict__ X,  const float* __restrict__ W1,
           const float* __restrict__ b1, const float* __restrict__ b2,
           const float* __restrict__ W3, const float* __restrict__ b3,
           const float* __restrict__ kT, float* __restrict__ out) {
    extern __shared__ char smem[];
    const uint32_t sb = smem_u32(smem);
    float* sC    = reinterpret_cast<float*>(smem + OFF_C);
    float* sConn = reinterpret_cast<float*>(smem + OFF_CONN);
    float* sLog  = reinterpret_cast<float*>(smem + OFF_LOG);
    float* sRed  = reinterpret_cast<float*>(smem + OFF_RED);

    const int tid  = threadIdx.x;                 // 256 threads, 8 warps
    const int wid  = tid >> 5;
    const int lane = tid & 31;
    const int la   = lane >> 2;                   // 0..7
    const int lb   = lane & 3;                    // 0..3
    const int wm   = wid & 3;                     // M block (32 rows)
    const int wn   = wid >> 2;                    // N block (64 cols)
    const int row0 = blockIdx.x * 128;            // 2 graphs per CTA

    // ---- staging helpers ----
    auto stageA = [&](int c, int ring) {          // X fp32 -> A ring
#pragma unroll
        for (int p = 0; p < 4; ++p) {
            int idx = tid + 256 * p;              // 0..1023 float4s
            int m = idx >> 3, kq = idx & 7;
            uint32_t dst = sb + RA(ring) + (uint32_t)(m * APITCH + 4 * kq) * 4u;
            const float* src = X + (size_t)(row0 + m) * HID + c * 32 + 4 * kq;
            CP16(dst, src);
        }
    };
    auto stageB1 = [&](int c, int ring) {         // g_w1h half -> B ring
#pragma unroll
        for (int p = 0; p < 2; ++p) {
            int idx = tid + 256 * p;              // 0..511 granules (16B)
            int n = idx >> 2, g = idx & 3;
            uint32_t dst = sb + RB(ring) + (uint32_t)(n * 80 + g * 16);
            const char* src = reinterpret_cast<const char*>(g_w1h) +
                              (size_t)n * 512 + c * 64 + g * 16;
            CP16(dst, src);
        }
    };
    auto stageW2 = [&](int c, int bi) {           // g_w2h half -> B buf bi
#pragma unroll
        for (int p = 0; p < 2; ++p) {
            int idx = tid + 256 * p;
            int n = idx >> 2, g = idx & 3;
            uint32_t dst = sb + RB(bi) + (uint32_t)(n * 80 + g * 16);
            const char* src = reinterpret_cast<const char*>(g_w2h) +
                              (size_t)n * 256 + c * 64 + g * 16;
            CP16(dst, src);
        }
        CPCOMMIT();
    };

    // ---- constants + degrees ----
    if (tid < 128) {
        sC[tid]       = b1[tid];
        sC[128 + tid] = b2[tid];
        sC[256 + tid] = W3[tid];
        sC[384 + tid] = W1[tid];                  // W1 row 0 (conn column)
    }
    float b3v = __ldg(b3);
    float ikT = 1.0f / __ldg(kT);
    int* sDeg = reinterpret_cast<int*>(smem + RA(2));
    if (tid < 128) sDeg[tid] = g_deg[row0 + tid];
    __syncthreads();                              // sDeg visible

    // kick pipeline: chunks 0,1 in flight while we compute ranks
    stageA(0, 0); stageB1(0, 0); CPCOMMIT();
    stageA(1, 1); stageB1(1, 1); CPCOMMIT();

    // ---- connectivity: stable per-graph degree rank (2 graphs) ----
    if (tid < 128) {
        int gg = tid >> 6, li = tid & 63, base = gg * 64;
        int di = sDeg[tid], rk = 0;
#pragma unroll 8
        for (int j = 0; j < GSIZE; ++j) {
            int dj = sDeg[base + j];
            rk += (dj < di) || (dj == di && j < li);
        }
        sConn[base + rk] = (float)li * (1.0f / 64.0f);
    }
    __syncthreads();                              // sConn visible

    // ---- GEMM1 acc init: b1[n] + conn[m] * W1row0[n]  (exact fp32) ----
    float acc[2][8][4];
    {
        float cn[2][2];
#pragma unroll
        for (int mt = 0; mt < 2; ++mt) {
            cn[mt][0] = sConn[wm * 32 + mt * 16 + la];
            cn[mt][1] = sConn[wm * 32 + mt * 16 + 8 + la];
        }
#pragma unroll
        for (int nt = 0; nt < 8; ++nt) {
            int n0 = wn * 64 + nt * 8 + 2 * lb;
            float w0 = sC[384 + n0], w1 = sC[384 + n0 + 1];
            float bb0 = sC[n0],      bb1 = sC[n0 + 1];
#pragma unroll
            for (int mt = 0; mt < 2; ++mt) {
                acc[mt][nt][0] = fmaf(cn[mt][0], w0, bb0);
                acc[mt][nt][1] = fmaf(cn[mt][0], w1, bb1);
                acc[mt][nt][2] = fmaf(cn[mt][1], w0, bb0);
                acc[mt][nt][3] = fmaf(cn[mt][1], w1, bb1);
            }
        }
    }

    // ---- GEMM1: [conn|X] @ W1, K=256 in 8 chunks of 32, 3-ring ----
#pragma unroll
    for (int c = 0; c < 8; ++c) {
        if (c < 7) { CPWAIT(1); } else { CPWAIT(0); }
        __syncthreads();                          // chunk c ready; MMA(c-1) done
        if (c < 6) { stageA(c + 2, (c + 2) % 3); stageB1(c + 2, (c + 2) % 3); CPCOMMIT(); }
        const float*    Af = reinterpret_cast<const float*>(smem + RA(c % 3));
        const uint32_t* Bt = reinterpret_cast<const uint32_t*>(smem + RB(c % 3));
#pragma unroll
        for (int kt = 0; kt < 2; ++kt) {          // 2 x k16
            int kb = kt * 16;
            uint32_t a[2][4];
#pragma unroll
            for (int mt = 0; mt < 2; ++mt) {
                int m0 = wm * 32 + mt * 16;
                float2 v0 = *reinterpret_cast<const float2*>(Af + (m0 + la) * APITCH + kb + 2 * lb);
                float2 v1 = *reinterpret_cast<const float2*>(Af + (m0 + 8 + la) * APITCH + kb + 2 * lb);
                float2 v2 = *reinterpret_cast<const float2*>(Af + (m0 + la) * APITCH + kb + 8 + 2 * lb);
                float2 v3 = *reinterpret_cast<const float2*>(Af + (m0 + 8 + la) * APITCH + kb + 8 + 2 * lb);
                a[mt][0] = cvt2(v0.x, v0.y);
                a[mt][1] = cvt2(v1.x, v1.y);
                a[mt][2] = cvt2(v2.x, v2.y);
                a[mt][3] = cvt2(v3.x, v3.y);
            }
#pragma unroll
            for (int nt = 0; nt < 8; ++nt) {
                int n0 = wn * 64 + nt * 8;
                uint32_t b0 = Bt[(n0 + la) * BPITCH2 + kt * 8 + lb];
                uint32_t b1 = Bt[(n0 + la) * BPITCH2 + kt * 8 + 4 + lb];
                mma16(acc[0][nt], a[0], b0, b1);
                mma16(acc[1][nt], a[1], b0, b1);
            }
        }
    }
    __syncthreads();                              // all MMA done before H/W2 writes

    // W2 chunks 0,1 in flight during epilogue1
    stageW2(0, 0);
    stageW2(1, 1);

    // ---- epilogue1: silu -> H (half2, overlays A ring) ----
    uint32_t* H2 = reinterpret_cast<uint32_t*>(smem);
#pragma unroll
    for (int mt = 0; mt < 2; ++mt) {
        int m0 = wm * 32 + mt * 16;
#pragma unroll
        for (int nt = 0; nt < 8; ++nt) {
            int nh = wn * 32 + nt * 4 + lb;       // half2 column index
            H2[(m0 + la) * HPITCH2 + nh]     = cvt2(silu(acc[mt][nt][0]), silu(acc[mt][nt][1]));
            H2[(m0 + 8 + la) * HPITCH2 + nh] = cvt2(silu(acc[mt][nt][2]), silu(acc[mt][nt][3]));
        }
    }

    // ---- GEMM2 acc init: b2[n] ----
#pragma unroll
    for (int nt = 0; nt < 8; ++nt) {
        int n0 = wn * 64 + nt * 8 + 2 * lb;
        float bb0 = sC[128 + n0], bb1 = sC[128 + n0 + 1];
#pragma unroll
        for (int mt = 0; mt < 2; ++mt) {
            acc[mt][nt][0] = bb0; acc[mt][nt][1] = bb1;
            acc[mt][nt][2] = bb0; acc[mt][nt][3] = bb1;
        }
    }

    // ---- GEMM2: H1 @ W2, K=128 in 4 chunks of 32, double-buffered ----
#pragma unroll
    for (int c = 0; c < 4; ++c) {
        if (c == 0) { CPWAIT(1); } else { CPWAIT(0); }
        __syncthreads();                          // W2 chunk ready; H visible; prev MMA done
        if (c == 1) stageW2(2, 0);
        if (c == 2) stageW2(3, 1);
        const uint32_t* Wt = reinterpret_cast<const uint32_t*>(smem + RB(c & 1));
#pragma unroll
        for (int kt = 0; kt < 2; ++kt) {
            int kh = c * 16 + kt * 8;             // half2 k-offset in H
            uint32_t a[2][4];
#pragma unroll
            for (int mt = 0; mt < 2; ++mt) {
                int m0 = wm * 32 + mt * 16;
                a[mt][0] = H2[(m0 + la) * HPITCH2 + kh + lb];
                a[mt][1] = H2[(m0 + 8 + la) * HPITCH2 + kh + lb];
                a[mt][2] = H2[(m0 + la) * HPITCH2 + kh + 4 + lb];
                a[mt][3] = H2[(m0 + 8 + la) * HPITCH2 + kh + 4 + lb];
            }
#pragma unroll
            for (int nt = 0; nt < 8; ++nt) {
                int n0 = wn * 64 + nt * 8;
                uint32_t b0 = Wt[(n0 + la) * BPITCH2 + kt * 8 + lb];
                uint32_t b1 = Wt[(n0 + la) * BPITCH2 + kt * 8 + 4 + lb];
                mma16(acc[0][nt], a[0], b0, b1);
                mma16(acc[1][nt], a[1], b0, b1);
            }
        }
    }
    __syncthreads();

    // ---- epilogue2: silu(D2) . W3 -> partials -> sRed ----
#pragma unroll
    for (int mt = 0; mt < 2; ++mt) {
#pragma unroll
        for (int half = 0; half < 2; ++half) {
            float p = 0.0f;
#pragma unroll
            for (int nt = 0; nt < 8; ++nt) {
                int n0 = wn * 64 + nt * 8 + 2 * lb;
                float v0 = acc[mt][nt][half * 2 + 0];
                float v1 = acc[mt][nt][half * 2 + 1];
                p = fmaf(silu(v0), sC[256 + n0], p);
                p = fmaf(silu(v1), sC[256 + n0 + 1], p);
            }
            int m = wm * 32 + mt * 16 + half * 8 + la;
            sRed[m * 8 + lb + 4 * wn] = p;
        }
    }
    __syncthreads();

    if (tid < 128) {
        float s = 0.0f;
#pragma unroll
        for (int t = 0; t < 8; ++t) s += sRed[tid * 8 + t];
        sLog[tid] = (s + b3v) * ikT;
    }
    __syncthreads();

    // ---- per-graph softmax ----
    if (tid < 64) {
        int w = tid >> 5, l = tid & 31, base = w * 64;
        float a  = sLog[base + l];
        float b  = sLog[base + l + 32];
        float mx = fmaxf(a, b);
#pragma unroll
        for (int o = 16; o; o >>= 1) mx = fmaxf(mx, __shfl_xor_sync(0xffffffffu, mx, o));
        float e0 = expf(a - mx), e1 = expf(b - mx);
        float s = e0 + e1;
#pragma unroll
        for (int o = 16; o; o >>= 1) s += __shfl_xor_sync(0xffffffffu, s, o);
        float inv = 1.0f / s;
        out[row0 + base + l]      = e0 * inv;
        out[row0 + base + l + 32] = e1 * inv;
    }
}

// ---------------- launcher ----------------
extern "C" void kernel_launch(void* const* d_in, const int* in_sizes, int n_in,
                              void* d_out, int out_size) {
    const float* X  = (const float*)d_in[0];
    const float* W1 = (const float*)d_in[1];
    const float* b1 = (const float*)d_in[2];
    const float* W2 = (const float*)d_in[3];
    const float* b2 = (const float*)d_in[4];
    const float* W3 = (const float*)d_in[5];
    const float* b3 = (const float*)d_in[6];
    const float* kT = (const float*)d_in[7];
    const int*   ei = (const int*)d_in[8];
    float* out = (float*)d_out;

    conv_kernel<<<128, 256>>>(W1, W2);            // zero deg + fp16 weights
    deg_kernel<<<EDGES / 4 / 256, 256>>>(ei);

    cudaFuncSetAttribute(mlp_kernel, cudaFuncAttributeMaxDynamicSharedMemorySize,
                         SMEM_BYTES);
    mlp_kernel<<<NGRAPH / 2, 256, SMEM_BYTES>>>(X, W1, b1, b2, W3, b3, kT, out);
}